// round 9
// baseline (speedup 1.0000x reference)
#include <cuda_runtime.h>
#include <cuda_bf16.h>
#include <cstdint>

#define NPIX 4096
#define CC   256
#define CQ   64
#define BB   8
#define ROWS_ALL 384
#define LD   72   // K/Q row stride (halves)
#define LDS  40   // S/VG row stride (halves), n-chunk 32 + 8 pad
#define NC   32   // n-chunk
#define ITERS (NPIX/NC)

// ================= scratch (device globals) =================
__device__ __nv_bfloat16 g_Qh[(size_t)BB*NPIX*CQ];   // [b][n][cq]
__device__ __nv_bfloat16 g_Ql[(size_t)BB*NPIX*CQ];
__device__ __nv_bfloat16 g_Kh[(size_t)BB*NPIX*CQ];   // [b][m][cq]
__device__ __nv_bfloat16 g_Kl[(size_t)BB*NPIX*CQ];
__device__ __nv_bfloat16 g_VGh[(size_t)BB*CC*NPIX];  // [b][c][n]
__device__ __nv_bfloat16 g_VGl[(size_t)BB*CC*NPIX];
__device__ float g_Wall[ROWS_ALL*CC];
__device__ float g_ball[ROWS_ALL];

// ================= PTX helpers =================
__device__ __forceinline__ uint32_t smem_u32(const void* p) {
    uint32_t a;
    asm("{ .reg .u64 t; cvta.to.shared.u64 t, %1; cvt.u32.u64 %0, t; }" : "=r"(a) : "l"(p));
    return a;
}
__device__ __forceinline__ void cpa16(uint32_t dst, const void* src) {
    asm volatile("cp.async.cg.shared.global [%0], [%1], 16;" :: "r"(dst), "l"(src));
}
#define CP_COMMIT() asm volatile("cp.async.commit_group;" ::: "memory")
#define CP_WAIT0()  asm volatile("cp.async.wait_group 0;" ::: "memory")
#define CP_WAIT1()  asm volatile("cp.async.wait_group 1;" ::: "memory")
#define MEMBAR_CTA() asm volatile("membar.cta;" ::: "memory")
#define BAR_SYNC(id)   asm volatile("bar.sync %0, 256;"   :: "r"(id) : "memory")
#define BAR_ARRIVE(id) asm volatile("bar.arrive %0, 256;" :: "r"(id) : "memory")
#define BAR_GRP(id)    asm volatile("bar.sync %0, 128;"   :: "r"(id) : "memory")
#define B_FULL0 1
#define B_FULL1 2
#define B_EMPTY0 3
#define B_EMPTY1 4
#define B_PROD  5
#define B_PRODW 6
#define B_CONSW 7

__device__ __forceinline__ void ldsm4(uint32_t r[4], uint32_t addr) {
    asm volatile("ldmatrix.sync.aligned.m8n8.x4.shared.b16 {%0,%1,%2,%3}, [%4];"
        : "=r"(r[0]), "=r"(r[1]), "=r"(r[2]), "=r"(r[3]) : "r"(addr));
}
__device__ __forceinline__ void mmab(float c[4], const uint32_t a[4],
                                     uint32_t b0, uint32_t b1) {
    asm volatile(
        "mma.sync.aligned.m16n8k16.row.col.f32.bf16.bf16.f32 "
        "{%0,%1,%2,%3}, {%4,%5,%6,%7}, {%8,%9}, {%0,%1,%2,%3};"
        : "+f"(c[0]), "+f"(c[1]), "+f"(c[2]), "+f"(c[3])
        : "r"(a[0]), "r"(a[1]), "r"(a[2]), "r"(a[3]), "r"(b0), "r"(b1));
}
__device__ __forceinline__ uint32_t packbf(float e0, float e1) {
    uint32_t r; asm("cvt.rn.bf16x2.f32 %0, %1, %2;" : "=r"(r) : "f"(e1), "f"(e0)); return r;
}
__device__ __forceinline__ float elu_raw(float v) {
    float kf = rintf(v * 1.44269504f);
    float r  = fmaf(kf, -0.693145752f, v);
    r        = fmaf(kf, -1.42860677e-6f, r);
    float p  = 1.38888894e-3f;
    p = fmaf(p, r, 8.33333377e-3f);
    p = fmaf(p, r, 4.16666679e-2f);
    p = fmaf(p, r, 0.166666672f);
    p = fmaf(p, r, 0.5f);
    p = fmaf(p, r, 1.0f);
    p = fmaf(p, r, 1.0f);
    float sc = __uint_as_float((uint32_t)((127 + (int)kf) << 23));
    float e  = fmaf(p, sc, -1.0f);
    return v > 0.f ? v : e;
}

// ================= Kernel 0: weights (gamma folded into V) =================
__global__ void build_weights(const float* __restrict__ qw, const float* __restrict__ qb,
                              const float* __restrict__ kw, const float* __restrict__ kb,
                              const float* __restrict__ vw, const float* __restrict__ vb,
                              const float* __restrict__ gw) {
    int r = blockIdx.x, d = threadIdx.x;
    if (r < CQ) {
        g_Wall[r*CC + d] = qw[r*CC + d];
        if (d == 0) g_ball[r] = qb[r];
    } else if (r < 2*CQ) {
        g_Wall[r*CC + d] = kw[(r-CQ)*CC + d];
        if (d == 0) g_ball[r] = kb[r-CQ];
    } else {
        int c = r - 2*CQ;
        float acc = 0.f;
        for (int cp = 0; cp < CC; ++cp) acc = fmaf(gw[c*CC + cp], vw[cp*CC + d], acc);
        g_Wall[r*CC + d] = acc;
        if (d == 0) {
            float bacc = 0.f;
            for (int cp = 0; cp < CC; ++cp) bacc = fmaf(gw[c*CC + cp], vb[cp], bacc);
            g_ball[r] = bacc;
        }
    }
}

// ================= Kernel 1: projection (fp32), writes split bf16 ==========
__global__ void __launch_bounds__(256) proj_kernel(const float* __restrict__ x) {
    __shared__ float Ws[16][64];
    __shared__ float Xs[16][64];
    int b = blockIdx.z, co0 = blockIdx.y * 64, n0 = blockIdx.x * 64;
    int t = threadIdx.x, tn = t % 16, tco = t / 16;
    const float* xb = x + (size_t)b * CC * NPIX;

    float acc[4][4];
    #pragma unroll
    for (int i = 0; i < 4; i++)
        #pragma unroll
        for (int j = 0; j < 4; j++) acc[i][j] = 0.f;

    for (int k0 = 0; k0 < CC; k0 += 16) {
        {
            int k = t % 16, co = t / 16;
            #pragma unroll
            for (int i = 0; i < 4; i++)
                Ws[k][co + 16*i] = g_Wall[(co0 + co + 16*i)*CC + k0 + k];
        }
        {
            int idx = t * 4, k = idx / 64, n = idx % 64;
            *(float4*)&Xs[k][n] = *(const float4*)&xb[(size_t)(k0 + k)*NPIX + n0 + n];
        }
        __syncthreads();
        #pragma unroll
        for (int k = 0; k < 16; k++) {
            float a[4], bx[4];
            #pragma unroll
            for (int i = 0; i < 4; i++) a[i] = Ws[k][tco + 16*i];
            #pragma unroll
            for (int j = 0; j < 4; j++) bx[j] = Xs[k][tn + 16*j];
            #pragma unroll
            for (int i = 0; i < 4; i++)
                #pragma unroll
                for (int j = 0; j < 4; j++) acc[i][j] = fmaf(a[i], bx[j], acc[i][j]);
        }
        __syncthreads();
    }

    #pragma unroll
    for (int i = 0; i < 4; i++) {
        int co = co0 + tco + 16*i;
        float bias = g_ball[co];
        #pragma unroll
        for (int j = 0; j < 4; j++) {
            int n = n0 + tn + 16*j;
            float s = acc[i][j] + bias;
            __nv_bfloat16 h = __float2bfloat16(s);
            __nv_bfloat16 l = __float2bfloat16(s - __bfloat162float(h));
            if (co < CQ) {
                size_t o = ((size_t)b*NPIX + n)*CQ + co;
                g_Qh[o] = h; g_Ql[o] = l;
            } else if (co < 2*CQ) {
                size_t o = ((size_t)b*NPIX + n)*CQ + (co - CQ);
                g_Kh[o] = h; g_Kl[o] = l;
            } else {
                size_t o = ((size_t)b*CC + (co - 2*CQ))*NPIX + n;
                g_VGh[o] = h; g_VGl[o] = l;
            }
        }
    }
}

// ================= Kernel 2: warp-specialized fused attention ==============
// smem (halves): K | Q x2 | S x2 | VG x2
#define SM_KH 0
#define SM_KL 4608
#define QH_ST(s) (9216  + (s)*4608)
#define QL_ST(s) (QH_ST(s) + 2304)
#define SH_ST(s) (18432 + (s)*5120)
#define SL_ST(s) (SH_ST(s) + 2560)
#define VH_ST(s) (28672 + (s)*20480)
#define VL_ST(s) (VH_ST(s) + 10240)
#define SMEM_HALVES 69632
#define SMEM_BYTES  (SMEM_HALVES*2)

__global__ void __launch_bounds__(256) attn_mma(float* __restrict__ out,
                                                const float* __restrict__ gbias) {
    extern __shared__ __nv_bfloat16 sm[];
    const uint32_t sb = smem_u32(sm);
    const int tid = threadIdx.x, wid = tid >> 5, lane = tid & 31;
    const int g = lane >> 2, t4 = lane & 3;
    const int b = blockIdx.y, m0 = blockIdx.x * 64;
    const int lrow = lane & 15, lcol = (lane >> 4) * 8;

    #define SMB(idx) (sb + (uint32_t)(idx) * 2u)

    if (wid < 4) {
        // ======================= PRODUCERS (warps 0-3) =====================
        const int ptid = tid;              // 0..127
        const int w1m = wid * 16;          // 16 m-rows per warp

        // prologue: K (whole) + Q(0)
        {
            const __nv_bfloat16* kh = g_Kh + ((size_t)b*NPIX + m0)*CQ;
            const __nv_bfloat16* kl = g_Kl + ((size_t)b*NPIX + m0)*CQ;
            #pragma unroll
            for (int r = 0; r < 4; r++) {
                int id = ptid + 128*r, row = id >> 3, ch = (id & 7) * 8;
                cpa16(SMB(SM_KH + row*LD + ch), kh + (size_t)row*CQ + ch);
                cpa16(SMB(SM_KL + row*LD + ch), kl + (size_t)row*CQ + ch);
            }
            const __nv_bfloat16* qh = g_Qh + (size_t)b*NPIX*CQ;
            const __nv_bfloat16* ql = g_Ql + (size_t)b*NPIX*CQ;
            #pragma unroll
            for (int r = 0; r < 2; r++) {
                int id = ptid + 128*r, row = id >> 3, ch = (id & 7) * 8;
                cpa16(SMB(QH_ST(0) + row*LD + ch), qh + (size_t)row*CQ + ch);
                cpa16(SMB(QL_ST(0) + row*LD + ch), ql + (size_t)row*CQ + ch);
            }
            CP_COMMIT();
        }

        for (int it = 0; it < ITERS; ++it) {
            const int buf = it & 1;
            BAR_GRP(B_PROD);   // all producers done reading Q slot buf^1
            if (it < ITERS-1) {
                const int n1 = (it + 1) * NC;
                const __nv_bfloat16* qh = g_Qh + ((size_t)b*NPIX + n1)*CQ;
                const __nv_bfloat16* ql = g_Ql + ((size_t)b*NPIX + n1)*CQ;
                #pragma unroll
                for (int r = 0; r < 2; r++) {
                    int id = ptid + 128*r, row = id >> 3, ch = (id & 7) * 8;
                    cpa16(SMB(QH_ST(buf^1) + row*LD + ch), qh + (size_t)row*CQ + ch);
                    cpa16(SMB(QL_ST(buf^1) + row*LD + ch), ql + (size_t)row*CQ + ch);
                }
                CP_COMMIT();
            }
            if (it < ITERS-1) { CP_WAIT1(); } else { CP_WAIT0(); }
            BAR_GRP(B_PRODW);  // ALL producers' K/Q[buf] data landed (cross-thread)
            if (it >= 2) BAR_SYNC(buf ? B_EMPTY1 : B_EMPTY0);

            // ---- GEMM1: D1[16m x 32n] = K·Q, 3-product ----
            float sacc[4][4];
            #pragma unroll
            for (int j = 0; j < 4; j++)
                #pragma unroll
                for (int q = 0; q < 4; q++) sacc[j][q] = 0.f;

            const uint32_t QH = QH_ST(buf), QL = QL_ST(buf);
            #pragma unroll
            for (int kk = 0; kk < 4; kk++) {
                const int C = kk * 16 + lcol;
                uint32_t kh[4], kl[4], qh0[4], qh1[4], ql0[4], ql1[4];
                ldsm4(kh,  SMB(SM_KH + (w1m + lrow)*LD + C));
                ldsm4(kl,  SMB(SM_KL + (w1m + lrow)*LD + C));
                ldsm4(qh0, SMB(QH + (lrow)*LD + C));
                ldsm4(qh1, SMB(QH + (16 + lrow)*LD + C));
                ldsm4(ql0, SMB(QL + (lrow)*LD + C));
                ldsm4(ql1, SMB(QL + (16 + lrow)*LD + C));
                mmab(sacc[0], kh, qh0[0], qh0[2]);
                mmab(sacc[1], kh, qh0[1], qh0[3]);
                mmab(sacc[2], kh, qh1[0], qh1[2]);
                mmab(sacc[3], kh, qh1[1], qh1[3]);
                mmab(sacc[0], kl, qh0[0], qh0[2]);
                mmab(sacc[1], kl, qh0[1], qh0[3]);
                mmab(sacc[2], kl, qh1[0], qh1[2]);
                mmab(sacc[3], kl, qh1[1], qh1[3]);
                mmab(sacc[0], kh, ql0[0], ql0[2]);
                mmab(sacc[1], kh, ql0[1], ql0[3]);
                mmab(sacc[2], kh, ql1[0], ql1[2]);
                mmab(sacc[3], kh, ql1[1], ql1[3]);
            }

            // ---- elu + split + store S[buf], layout [m][n] ----
            const uint32_t SH = SH_ST(buf), SL = SL_ST(buf);
            #pragma unroll
            for (int j = 0; j < 4; j++) {
                int col = 8*j + t4*2;
                {
                    float e0 = elu_raw(sacc[j][0]);
                    float e1 = elu_raw(sacc[j][1]);
                    uint32_t ph = packbf(e0, e1);
                    float l0 = e0 - __uint_as_float(ph << 16);
                    float l1 = e1 - __uint_as_float(ph & 0xFFFF0000u);
                    int row = w1m + g;
                    *(uint32_t*)&sm[SH + row*LDS + col] = ph;
                    *(uint32_t*)&sm[SL + row*LDS + col] = packbf(l0, l1);
                }
                {
                    float e0 = elu_raw(sacc[j][2]);
                    float e1 = elu_raw(sacc[j][3]);
                    uint32_t ph = packbf(e0, e1);
                    float l0 = e0 - __uint_as_float(ph << 16);
                    float l1 = e1 - __uint_as_float(ph & 0xFFFF0000u);
                    int row = w1m + g + 8;
                    *(uint32_t*)&sm[SH + row*LDS + col] = ph;
                    *(uint32_t*)&sm[SL + row*LDS + col] = packbf(l0, l1);
                }
            }
            MEMBAR_CTA();   // make S stores visible before arrival (bar.arrive has no drain)
            BAR_ARRIVE(buf ? B_FULL1 : B_FULL0);
        }
    } else {
        // ======================= CONSUMERS (warps 4-7) =====================
        const int ctid = tid - 128;        // 0..127
        const int w2c = (wid - 4) * 64;    // 64 c-rows per warp

        // prologue: VG(0)
        {
            const __nv_bfloat16* vh = g_VGh + (size_t)b*CC*NPIX;
            const __nv_bfloat16* vl = g_VGl + (size_t)b*CC*NPIX;
            #pragma unroll
            for (int r = 0; r < 8; r++) {
                int id = ctid + 128*r, row = id >> 2, ch = (id & 3) * 8;
                cpa16(SMB(VH_ST(0) + row*LDS + ch), vh + (size_t)row*NPIX + ch);
                cpa16(SMB(VL_ST(0) + row*LDS + ch), vl + (size_t)row*NPIX + ch);
            }
            CP_COMMIT();
        }

        float acc[4][8][4];
        #pragma unroll
        for (int i = 0; i < 4; i++)
            #pragma unroll
            for (int j = 0; j < 8; j++)
                #pragma unroll
                for (int q = 0; q < 4; q++) acc[i][j][q] = 0.f;

        for (int it = 0; it < ITERS; ++it) {
            const int buf = it & 1;
            BAR_SYNC(buf ? B_FULL1 : B_FULL0);   // S[buf] ready + all-consumer rendezvous
            if (it < ITERS-1) {
                const int n1 = (it + 1) * NC;
                const __nv_bfloat16* vh = g_VGh + (size_t)b*CC*NPIX + n1;
                const __nv_bfloat16* vl = g_VGl + (size_t)b*CC*NPIX + n1;
                #pragma unroll
                for (int r = 0; r < 8; r++) {
                    int id = ctid + 128*r, row = id >> 2, ch = (id & 3) * 8;
                    cpa16(SMB(VH_ST(buf^1) + row*LDS + ch), vh + (size_t)row*NPIX + ch);
                    cpa16(SMB(VL_ST(buf^1) + row*LDS + ch), vl + (size_t)row*NPIX + ch);
                }
                CP_COMMIT();
            }
            if (it < ITERS-1) { CP_WAIT1(); } else { CP_WAIT0(); }
            BAR_GRP(B_CONSW);  // ALL consumers' VG[buf] data landed (cross-thread)

            // ---- GEMM2: O[64c x 64m] += VG·S, 3-product ----
            const uint32_t VH = VH_ST(buf), VL = VL_ST(buf);
            const uint32_t SH = SH_ST(buf), SL = SL_ST(buf);
            #pragma unroll
            for (int kk = 0; kk < 2; kk++) {
                const int C = kk * 16 + lcol;
                uint32_t vh[4][4], vl[4][4], sh[4][4], sl[4][4];
                #pragma unroll
                for (int i = 0; i < 4; i++) {
                    ldsm4(vh[i], SMB(VH + (w2c + 16*i + lrow)*LDS + C));
                    ldsm4(vl[i], SMB(VL + (w2c + 16*i + lrow)*LDS + C));
                }
                #pragma unroll
                for (int s = 0; s < 4; s++) {
                    ldsm4(sh[s], SMB(SH + (16*s + lrow)*LDS + C));
                    ldsm4(sl[s], SMB(SL + (16*s + lrow)*LDS + C));
                }
                #pragma unroll
                for (int i = 0; i < 4; i++)
                    #pragma unroll
                    for (int s = 0; s < 4; s++) {
                        mmab(acc[i][2*s],   vh[i], sh[s][0], sh[s][2]);
                        mmab(acc[i][2*s+1], vh[i], sh[s][1], sh[s][3]);
                        mmab(acc[i][2*s],   vl[i], sh[s][0], sh[s][2]);
                        mmab(acc[i][2*s+1], vl[i], sh[s][1], sh[s][3]);
                        mmab(acc[i][2*s],   vh[i], sl[s][0], sl[s][2]);
                        mmab(acc[i][2*s+1], vh[i], sl[s][1], sl[s][3]);
                    }
            }
            BAR_ARRIVE(buf ? B_EMPTY1 : B_EMPTY0);
        }

        // ---- epilogue: out = acc/4096 + gbias[c] ----
        const float inv = 1.0f / 4096.0f;
        #pragma unroll
        for (int i = 0; i < 4; i++) {
            int c  = w2c + 16*i + g;
            float b0 = gbias[c], b8 = gbias[c + 8];
            #pragma unroll
            for (int j = 0; j < 8; j++) {
                int m = m0 + 8*j + t4*2;
                float2 v0 = { fmaf(acc[i][j][0], inv, b0), fmaf(acc[i][j][1], inv, b0) };
                *(float2*)&out[((size_t)b*CC + c)*NPIX + m] = v0;
                float2 v1 = { fmaf(acc[i][j][2], inv, b8), fmaf(acc[i][j][3], inv, b8) };
                *(float2*)&out[((size_t)b*CC + c + 8)*NPIX + m] = v1;
            }
        }
    }
}

// ================= launch =================
extern "C" void kernel_launch(void* const* d_in, const int* in_sizes, int n_in,
                              void* d_out, int out_size) {
    const float* x  = (const float*)d_in[0];
    const float* qw = (const float*)d_in[1];
    const float* qb = (const float*)d_in[2];
    const float* kw = (const float*)d_in[3];
    const float* kb = (const float*)d_in[4];
    const float* vw = (const float*)d_in[5];
    const float* vb = (const float*)d_in[6];
    const float* gw = (const float*)d_in[7];
    const float* gb = (const float*)d_in[8];
    float* out = (float*)d_out;

    cudaFuncSetAttribute(attn_mma, cudaFuncAttributeMaxDynamicSharedMemorySize, SMEM_BYTES);

    build_weights<<<ROWS_ALL, 256>>>(qw, qb, kw, kb, vw, vb, gw);
    proj_kernel<<<dim3(64, 6, BB), 256>>>(x);
    attn_mma<<<dim3(64, BB), 256, SMEM_BYTES>>>(out, gb);
}